// round 14
// baseline (speedup 1.0000x reference)
#include <cuda_runtime.h>
#include <cuda_fp16.h>
#include <cstdint>
#include <cstddef>

#define NN   100000
#define HIDD 128
#define EE   400000
#define GG   512

// ---------------- device scratch (static, no allocations) ----------------
__device__ __half d_xh[2][6][NN * HIDD];          // ping-pong node features (fp16, post-relu)
__device__ float d_init[4][NN * HIDD];            // pre-relu embed (fp32, readout contribution)
__device__ float d_g[GG * HIDD];                  // graph readout accumulator
__device__ int   d_deg[24][NN];
__device__ float d_rdeg[24][NN];
__device__ int   d_off[24][NN + 1];               // CSR offsets (by dst)
__device__ int   d_cur[24][NN];                   // fill cursors
__device__ int   d_csr_src[24][EE];               // src ids sorted by dst
__device__ int   d_bsum[24][128];                 // scan block sums
__device__ float d_wrsum[3][6][HIDD * HIDD];      // sum of Wr over edge types with dst=t
__device__ float d_blsum[3][6][HIDD];             // sum of bl over edge types with dst=t
// split-fp16 weights (hi+lo ~22 bits), m16n8k16 B-frag order, interleaved {hi.x,hi.y,lo.x,lo.y}
__device__ uint4 d_bfrag[90][4096];

// ---------------- edge-type tables ----------------
// type ids: 0 ssBox, 1 place_frame, 2 object, 3 ssCylinder, 4 pick, 5 place
__constant__ int c_src[24] = {2,0,1,0,1,2,4,5,2,0,1,3,2,4,1,4,3,4,2,5,3,5,1,5};
__constant__ int c_dstcnt[6] = {3,5,5,3,4,4};
__constant__ int c_dstedges[6][5] = {
    {0,2,9,-1,-1},{3,5,10,15,23},{1,4,8,13,19},{11,17,21,-1,-1},{7,12,14,16,-1},{6,18,20,22,-1}};

__device__ __forceinline__ uint32_t smem_u32(const void* p) {
    uint32_t a;
    asm("{ .reg .u64 t; cvta.to.shared.u64 t, %1; cvt.u32.u64 %0, t; }" : "=r"(a) : "l"(p));
    return a;
}
__device__ __forceinline__ uint32_t pack_half2(float a, float b) {
    union { __half2 h; uint32_t u; } v;
    v.h = __floats2half2_rn(a, b);           // a -> low half, b -> high
    return v.u;
}

// ---------------- prep kernels ----------------
__global__ void k_wrsum(const float* __restrict__ Wr, const float* __restrict__ bl) {
    int bid = blockIdx.x;               // 0..17
    int layer = bid / 6, t = bid % 6;
    int cnt = c_dstcnt[t];
    for (int e = threadIdx.x; e < HIDD * HIDD; e += blockDim.x) {
        float sv = 0.f;
        for (int q = 0; q < cnt; q++) {
            int i = c_dstedges[t][q];
            sv += Wr[(size_t)(layer * 24 + i) * HIDD * HIDD + e];
        }
        d_wrsum[layer][t][e] = sv;
    }
    if (threadIdx.x < HIDD) {
        float sv = 0.f;
        for (int q = 0; q < cnt; q++) {
            int i = c_dstedges[t][q];
            sv += bl[(size_t)(layer * 24 + i) * HIDD + threadIdx.x];
        }
        d_blsum[layer][t][threadIdx.x] = sv;
    }
}

// weight prep: split-fp16 (hi = fp16(w), lo = fp16(w - hi)), m16n8k16 B-fragment order
__global__ void k_wprep(const float* __restrict__ Wl) {
    int m = blockIdx.x;                 // 0..89: 0..71 = Wl[layer*24+i], 72..89 = wrsum
    const float* src = (m < 72) ? (Wl + (size_t)m * HIDD * HIDD)
                                : (&d_wrsum[0][0][0] + (size_t)(m - 72) * HIDD * HIDD);
    uint32_t* dst = (uint32_t*)d_bfrag[m];
    for (int idx = threadIdx.x; idx < 8192; idx += blockDim.x) {
        int r = idx & 1, lane = (idx >> 1) & 31, j = (idx >> 6) & 15, ks = idx >> 10;
        int fidx = idx >> 1;
        int n = j * 8 + (lane >> 2);
        int k = ks * 16 + (lane & 3) * 2 + r * 8;
        float w0 = src[k * HIDD + n];
        float w1 = src[(k + 1) * HIDD + n];
        __half h0 = __float2half_rn(w0);
        __half h1 = __float2half_rn(w1);
        float l0f = w0 - __half2float(h0);
        float l1f = w1 - __half2float(h1);
        union { __half b[2]; uint32_t u; } uh;
        uh.b[0] = h0; uh.b[1] = h1;
        dst[fidx * 4 + r] = uh.u;                     // hi at .x/.y
        dst[fidx * 4 + 2 + r] = pack_half2(l0f, l1f); // lo at .z/.w
    }
}

// ---------------- embedding (fp16 x, fp32 pre-relu init) ----------------
struct EmbedArgs {
    const float* feat[4];
    const float* W[6];
    const float* b[6];
    const int*   times;
};

__global__ void k_embed(EmbedArgs ea) {
    __shared__ float sf[64][8];
    int t = blockIdx.y;
    int tid = threadIdx.x;
    int base = blockIdx.x * 64;
    const int FDs[6] = {4,4,4,3,0,0};
    const int Ds[6]  = {8,8,8,7,4,4};
    int FD = FDs[t], D = Ds[t];
    if (tid < 64) {
        int n = base + tid;
        if (n < NN) {
            float p = (float)ea.times[(size_t)t * NN + n];
            const float div1 = 0.01f;            // 10000^(-2/4)
            float p1 = p * div1;
            for (int dd = 0; dd < FD; ++dd) sf[tid][dd] = ea.feat[t][(size_t)n * FD + dd];
            sf[tid][FD + 0] = sinf(p);
            sf[tid][FD + 1] = cosf(p);
            sf[tid][FD + 2] = sinf(p1);
            sf[tid][FD + 3] = cosf(p1);
            for (int dd = D; dd < 8; ++dd) sf[tid][dd] = 0.f;
        }
    }
    __syncthreads();
    int j = tid;                                  // 0..127
    float Wj[8];
    float bj = ea.b[t][j];
    for (int dd = 0; dd < 8; ++dd) Wj[dd] = (dd < D) ? ea.W[t][dd * HIDD + j] : 0.f;
    int nmax = NN - base; if (nmax > 64) nmax = 64;
    for (int u = 0; u < nmax; ++u) {
        int n = base + u;
        float h = bj;
        #pragma unroll
        for (int dd = 0; dd < 8; ++dd) h += sf[u][dd] * Wj[dd];
        d_xh[0][t][(size_t)n * HIDD + j] = __float2half_rn(fmaxf(h, 0.f));
        if (t < 4) d_init[t][(size_t)n * HIDD + j] = h;
    }
}

// ---------------- degree + CSR build ----------------
__global__ void k_zero() {
    int idx = blockIdx.x * blockDim.x + threadIdx.x;
    if (idx < GG * HIDD) d_g[idx] = 0.f;
    if (idx < 24 * NN)  (&d_deg[0][0])[idx] = 0;
}

__global__ void k_deg(const int* __restrict__ edges) {
    int e = blockIdx.x * blockDim.x + threadIdx.x;
    int i = blockIdx.y;
    if (e < EE) {
        int d = edges[(size_t)i * 2 * EE + EE + e];
        atomicAdd(&d_deg[i][d], 1);
    }
}

__global__ void k_rdeg() {
    int idx = blockIdx.x * blockDim.x + threadIdx.x;
    if (idx < 24 * NN) {
        int dg = (&d_deg[0][0])[idx];
        (&d_rdeg[0][0])[idx] = 1.0f / (float)(dg > 1 ? dg : 1);
    }
}

__global__ void k_scan1() {
    __shared__ int sh[1024];
    int i = blockIdx.y;
    int d = blockIdx.x * 1024 + threadIdx.x;
    int v = (d < NN) ? d_deg[i][d] : 0;
    sh[threadIdx.x] = v;
    __syncthreads();
    #pragma unroll
    for (int off = 1; off < 1024; off <<= 1) {
        int x2 = (threadIdx.x >= off) ? sh[threadIdx.x - off] : 0;
        __syncthreads();
        sh[threadIdx.x] += x2;
        __syncthreads();
    }
    if (d < NN) d_off[i][d] = sh[threadIdx.x];      // inclusive (temp)
    if (threadIdx.x == 1023) d_bsum[i][blockIdx.x] = sh[1023];
}

__global__ void k_scan2() {
    int i = blockIdx.x;
    if (threadIdx.x == 0) {
        int run = 0;
        for (int b = 0; b < 98; b++) {
            int v = d_bsum[i][b];
            d_bsum[i][b] = run;
            run += v;
        }
    }
}

__global__ void k_scan3() {
    int i = blockIdx.y;
    int d = blockIdx.x * 1024 + threadIdx.x;
    if (d < NN) {
        int excl = d_off[i][d] - d_deg[i][d] + d_bsum[i][blockIdx.x];
        d_off[i][d] = excl;
        d_cur[i][d] = excl;
    }
    if (blockIdx.x == 0 && threadIdx.x == 0) d_off[i][NN] = EE;
}

__global__ void k_fill(const int* __restrict__ edges) {
    int e = blockIdx.x * blockDim.x + threadIdx.x;
    int i = blockIdx.y;
    if (e < EE) {
        const int* eb = edges + (size_t)i * 2 * EE;
        int s = eb[e];
        int d = eb[EE + e];
        int pos = atomicAdd(&d_cur[i][d], 1);
        d_csr_src[i][pos] = s;
    }
}

// ---------------- fused gather+GEMM ----------------
// x[pout][t] = relu( sum_i mean_i(x[src_i])@Wl_i + x[t]@WrSum + blsum )
// Each CTA gathers its own 128-row A tile per group directly into SMEM.
#define ASTRIDE 136
#define SMEM_TOTAL 34816

__global__ __launch_bounds__(256, 2)
void k_gemm_mma(int layer, int pin, int pout) {
    extern __shared__ char smem[];
    uint32_t sb = smem_u32(smem);
    int tid = threadIdx.x, wid = tid >> 5, l = tid & 31;
    int t = blockIdx.y;
    int r0 = blockIdx.x * 128;
    int cnt = c_dstcnt[t];
    int wr = wid & 3, wc = wid >> 2;

    float acc[2][8][4];
    #pragma unroll
    for (int mt = 0; mt < 2; mt++)
        #pragma unroll
        for (int j = 0; j < 8; j++)
            #pragma unroll
            for (int r = 0; r < 4; r++) acc[mt][j][r] = 0.f;

    #pragma unroll 1
    for (int g = 0; g <= cnt; g++) {
        int mat;
        if (g < cnt) {
            // ---- gather A tile: warp wid handles rows wid*16 .. wid*16+15 ----
            int i = c_dstedges[t][g];
            mat = layer * 24 + i;
            const int* offs = d_off[i];
            const int* srcs = d_csr_src[i];
            const uint2* xb = (const uint2*)d_xh[pin][c_src[i]];   // 4 fp16 per lane
            #pragma unroll 1
            for (int rr = 0; rr < 16; rr++) {
                int row = wid * 16 + rr;
                int d = r0 + row;
                float4 s4 = make_float4(0.f, 0.f, 0.f, 0.f);
                float rd = 0.f;
                if (d < NN) {
                    int st = __ldg(offs + d);
                    int en = __ldg(offs + d + 1);
                    int e = st;
                    for (; e + 3 < en; e += 4) {
                        int s0 = __ldg(srcs + e);
                        int s1 = __ldg(srcs + e + 1);
                        int s2 = __ldg(srcs + e + 2);
                        int s3 = __ldg(srcs + e + 3);
                        uint2 u0 = __ldg(xb + (size_t)s0 * 32 + l);
                        uint2 u1 = __ldg(xb + (size_t)s1 * 32 + l);
                        uint2 u2 = __ldg(xb + (size_t)s2 * 32 + l);
                        uint2 u3 = __ldg(xb + (size_t)s3 * 32 + l);
                        #pragma unroll
                        for (int z = 0; z < 4; z++) {
                            uint2 u = (z == 0) ? u0 : (z == 1) ? u1 : (z == 2) ? u2 : u3;
                            float2 f0 = __half22float2(*(__half2*)&u.x);
                            float2 f1 = __half22float2(*(__half2*)&u.y);
                            s4.x += f0.x; s4.y += f0.y; s4.z += f1.x; s4.w += f1.y;
                        }
                    }
                    for (; e < en; e++) {
                        int s0 = __ldg(srcs + e);
                        uint2 u = __ldg(xb + (size_t)s0 * 32 + l);
                        float2 f0 = __half22float2(*(__half2*)&u.x);
                        float2 f1 = __half22float2(*(__half2*)&u.y);
                        s4.x += f0.x; s4.y += f0.y; s4.z += f1.x; s4.w += f1.y;
                    }
                    rd = __ldg(&d_rdeg[i][d]);
                }
                uint2 o;
                o.x = pack_half2(s4.x * rd, s4.y * rd);
                o.y = pack_half2(s4.z * rd, s4.w * rd);
                *(uint2*)(smem + (size_t)(row * ASTRIDE + l * 4) * 2) = o;
            }
        } else {
            // ---- WrSum group: plain fp16 tile copy ----
            mat = 72 + layer * 6 + t;
            const uint4* As = (const uint4*)d_xh[pin][t];
            #pragma unroll
            for (int q = 0; q < 8; q++) {
                int idx = tid + q * 256;          // 2048 = 128 rows x 16 uint4
                int row = idx >> 4, c = idx & 15;
                uint4 v = make_uint4(0u, 0u, 0u, 0u);
                int gr = r0 + row;
                if (gr < NN) v = __ldg(As + (size_t)gr * 16 + c);
                *(uint4*)(smem + (size_t)(row * ASTRIDE + c * 8) * 2) = v;
            }
        }
        __syncthreads();

        const uint4* Bf = d_bfrag[mat];
        #pragma unroll
        for (int ks = 0; ks < 8; ks++) {
            uint32_t ah[2][4];
            #pragma unroll
            for (int mt = 0; mt < 2; mt++) {
                uint32_t off = (uint32_t)(((wr * 32 + mt * 16 + (l & 15)) * ASTRIDE
                                           + ks * 16 + (l >> 4) * 8) * 2);
                asm volatile("ldmatrix.sync.aligned.m8n8.x4.shared.b16 {%0,%1,%2,%3}, [%4];"
                    : "=r"(ah[mt][0]), "=r"(ah[mt][1]), "=r"(ah[mt][2]), "=r"(ah[mt][3])
                    : "r"(sb + off));
            }
            #pragma unroll
            for (int j = 0; j < 8; j++) {
                int fidx = (ks * 16 + wc * 8 + j) * 32 + l;
                uint4 b = __ldg(Bf + fidx);   // {hi.x, hi.y, lo.x, lo.y}
                #pragma unroll
                for (int mt = 0; mt < 2; mt++) {
                    float* c = acc[mt][j];
                    asm volatile("mma.sync.aligned.m16n8k16.row.col.f32.f16.f16.f32 "
                        "{%0,%1,%2,%3}, {%4,%5,%6,%7}, {%8,%9}, {%0,%1,%2,%3};"
                        : "+f"(c[0]), "+f"(c[1]), "+f"(c[2]), "+f"(c[3])
                        : "r"(ah[mt][0]), "r"(ah[mt][1]), "r"(ah[mt][2]), "r"(ah[mt][3]),
                          "r"(b.x), "r"(b.y));
                    asm volatile("mma.sync.aligned.m16n8k16.row.col.f32.f16.f16.f32 "
                        "{%0,%1,%2,%3}, {%4,%5,%6,%7}, {%8,%9}, {%0,%1,%2,%3};"
                        : "+f"(c[0]), "+f"(c[1]), "+f"(c[2]), "+f"(c[3])
                        : "r"(ah[mt][0]), "r"(ah[mt][1]), "r"(ah[mt][2]), "r"(ah[mt][3]),
                          "r"(b.z), "r"(b.w));
                }
            }
        }
        __syncthreads();
    }

    // ---- single epilogue: bias + relu + fp16 store ----
    __half* X = d_xh[pout][t];
    const float* bias = d_blsum[layer][t];
    #pragma unroll
    for (int mt = 0; mt < 2; mt++) {
        int gr = r0 + wr * 32 + mt * 16 + (l >> 2);
        #pragma unroll
        for (int j = 0; j < 8; j++) {
            int tcol = wc * 64 + j * 8 + (l & 3) * 2;
            float b0 = bias[tcol], b1 = bias[tcol + 1];
            float* c = acc[mt][j];
            if (gr < NN)
                ((uint32_t*)(X + (size_t)gr * HIDD))[tcol >> 1] =
                    pack_half2(fmaxf(c[0] + b0, 0.f), fmaxf(c[1] + b1, 0.f));
            if (gr + 8 < NN)
                ((uint32_t*)(X + (size_t)(gr + 8) * HIDD))[tcol >> 1] =
                    pack_half2(fmaxf(c[2] + b0, 0.f), fmaxf(c[3] + b1, 0.f));
        }
    }
}

// ---------------- readout: warp per node, vectorized reduction into g ----------------
__global__ void k_gpp(int pfin, const int* __restrict__ batch) {
    int gw = (blockIdx.x * blockDim.x + threadIdx.x) >> 5;   // node slot 0..6*NN-1
    if (gw >= 6 * NN) return;
    int lane = threadIdx.x & 31;
    int t = gw / NN, n = gw - t * NN;
    float4 v;
    if (t < 4) {
        v = *(const float4*)(d_init[t] + (size_t)n * HIDD + lane * 4);
    } else {
        uint2 u = __ldg((const uint2*)d_xh[pfin][t] + (size_t)n * 32 + lane);
        float2 f0 = __half22float2(*(__half2*)&u.x);
        float2 f1 = __half22float2(*(__half2*)&u.y);
        v = make_float4(f0.x, f0.y, f1.x, f1.y);
    }
    int bg = __ldg(batch + (size_t)t * NN + n);
    float* op = d_g + (size_t)bg * HIDD + lane * 4;
    asm volatile("red.global.add.v4.f32 [%0], {%1,%2,%3,%4};"
                 :: "l"(op), "f"(v.x), "f"(v.y), "f"(v.z), "f"(v.w) : "memory");
}

// ---------------- graph MLP head ----------------
__global__ void k_mlp(float* __restrict__ out,
                      const float* __restrict__ W1, const float* __restrict__ b1,
                      const float* __restrict__ W2, const float* __restrict__ b2) {
    __shared__ float s[4][HIDD];
    int warp = threadIdx.x >> 5, lane = threadIdx.x & 31;
    int gidx = blockIdx.x * 4 + warp;
    if (gidx >= GG) return;
    #pragma unroll
    for (int q = 0; q < 4; q++) {
        float v = d_g[(size_t)gidx * HIDD + lane + q * 32];
        s[warp][lane + q * 32] = fmaxf(v, 0.f);
    }
    __syncwarp();
    float h = b1[lane];
    #pragma unroll 8
    for (int k = 0; k < HIDD; k++) h += s[warp][k] * W1[k * 32 + lane];
    h = fmaxf(h, 0.f);
    float val = h * W2[lane];
    #pragma unroll
    for (int off = 16; off; off >>= 1) val += __shfl_xor_sync(0xffffffffu, val, off);
    if (lane == 0) out[gidx] = val + b2[0];
}

// ---------------- launch ----------------
extern "C" void kernel_launch(void* const* d_in, const int* in_sizes, int n_in,
                              void* d_out, int out_size) {
    const float* Wl   = (const float*)d_in[16];
    const float* bl   = (const float*)d_in[17];
    const float* Wr   = (const float*)d_in[18];
    const float* W1   = (const float*)d_in[19];
    const float* b1   = (const float*)d_in[20];
    const float* W2   = (const float*)d_in[21];
    const float* b2   = (const float*)d_in[22];
    const int* times  = (const int*)d_in[23];
    const int* edges  = (const int*)d_in[24];
    const int* batch  = (const int*)d_in[25];

    cudaFuncSetAttribute(k_gemm_mma, cudaFuncAttributeMaxDynamicSharedMemorySize, SMEM_TOTAL);

    k_zero<<<9375, 256>>>();
    k_deg<<<dim3(391, 24), 1024>>>(edges);
    k_rdeg<<<9375, 256>>>();
    k_scan1<<<dim3(98, 24), 1024>>>();
    k_scan2<<<24, 32>>>();
    k_scan3<<<dim3(98, 24), 1024>>>();
    k_fill<<<dim3(391, 24), 1024>>>(edges);

    k_wrsum<<<18, 256>>>(Wr, bl);
    k_wprep<<<90, 256>>>(Wl);

    EmbedArgs ea;
    for (int t = 0; t < 4; t++) ea.feat[t] = (const float*)d_in[t];
    for (int t = 0; t < 6; t++) {
        ea.W[t] = (const float*)d_in[4 + 2 * t];
        ea.b[t] = (const float*)d_in[5 + 2 * t];
    }
    ea.times = times;
    k_embed<<<dim3(1563, 6), 128>>>(ea);

    int pin = 0;
    for (int layer = 0; layer < 3; ++layer) {
        int pout = pin ^ 1;
        k_gemm_mma<<<dim3(782, 6), 256, SMEM_TOTAL>>>(layer, pin, pout);
        pin = pout;
    }

    k_gpp<<<75000, 256>>>(pin, batch);
    k_mlp<<<128, 128>>>((float*)d_out, W1, b1, W2, b2);
}

// round 15
// speedup vs baseline: 1.4824x; 1.4824x over previous
#include <cuda_runtime.h>
#include <cuda_fp16.h>
#include <cstdint>
#include <cstddef>

#define NN   100000
#define HIDD 128
#define EE   400000
#define GG   512

// ---------------- device scratch (static, no allocations) ----------------
__device__ __half d_xh[2][6][NN * HIDD];          // ping-pong node features (fp16, post-relu)
__device__ __half d_agg[24][NN * HIDD];           // per-edge-type aggregated means (fp16)
__device__ float d_init[4][NN * HIDD];            // pre-relu embed (readout contribution)
__device__ float d_g[GG * HIDD];                  // graph readout accumulator
__device__ int   d_deg[24][NN];
__device__ float d_rdeg[24][NN];
__device__ int   d_off[24][NN + 1];               // CSR offsets (by dst)
__device__ int   d_cur[24][NN];                   // fill cursors
__device__ int   d_csr_src[24][EE];               // src ids sorted by dst
__device__ int   d_bsum[24][128];                 // scan block sums
__device__ float d_wrsum[3][6][HIDD * HIDD];      // sum of Wr over edge types with dst=t
__device__ float d_blsum[3][6][HIDD];             // sum of bl over edge types with dst=t
// split-fp16 weights (hi+lo ~22 bits), m16n8k16 B-frag order, interleaved {hi.x,hi.y,lo.x,lo.y}
__device__ uint4 d_bfrag[90][4096];

// ---------------- edge-type tables ----------------
// type ids: 0 ssBox, 1 place_frame, 2 object, 3 ssCylinder, 4 pick, 5 place
__constant__ int c_src[24] = {2,0,1,0,1,2,4,5,2,0,1,3,2,4,1,4,3,4,2,5,3,5,1,5};
__constant__ int c_dstcnt[6] = {3,5,5,3,4,4};
__constant__ int c_dstedges[6][5] = {
    {0,2,9,-1,-1},{3,5,10,15,23},{1,4,8,13,19},{11,17,21,-1,-1},{7,12,14,16,-1},{6,18,20,22,-1}};

__device__ __forceinline__ uint32_t smem_u32(const void* p) {
    uint32_t a;
    asm("{ .reg .u64 t; cvta.to.shared.u64 t, %1; cvt.u32.u64 %0, t; }" : "=r"(a) : "l"(p));
    return a;
}
__device__ __forceinline__ uint32_t pack_half2(float a, float b) {
    union { __half2 h; uint32_t u; } v;
    v.h = __floats2half2_rn(a, b);           // a -> low half, b -> high
    return v.u;
}

// ---------------- prep kernels ----------------
__global__ void k_wrsum(const float* __restrict__ Wr, const float* __restrict__ bl) {
    int bid = blockIdx.x;               // 0..17
    int layer = bid / 6, t = bid % 6;
    int cnt = c_dstcnt[t];
    for (int e = threadIdx.x; e < HIDD * HIDD; e += blockDim.x) {
        float sv = 0.f;
        for (int q = 0; q < cnt; q++) {
            int i = c_dstedges[t][q];
            sv += Wr[(size_t)(layer * 24 + i) * HIDD * HIDD + e];
        }
        d_wrsum[layer][t][e] = sv;
    }
    if (threadIdx.x < HIDD) {
        float sv = 0.f;
        for (int q = 0; q < cnt; q++) {
            int i = c_dstedges[t][q];
            sv += bl[(size_t)(layer * 24 + i) * HIDD + threadIdx.x];
        }
        d_blsum[layer][t][threadIdx.x] = sv;
    }
}

// weight prep: split-fp16 (hi = fp16(w), lo = fp16(w - hi)), m16n8k16 B-fragment order
__global__ void k_wprep(const float* __restrict__ Wl) {
    int m = blockIdx.x;                 // 0..89: 0..71 = Wl[layer*24+i], 72..89 = wrsum
    const float* src = (m < 72) ? (Wl + (size_t)m * HIDD * HIDD)
                                : (&d_wrsum[0][0][0] + (size_t)(m - 72) * HIDD * HIDD);
    uint32_t* dst = (uint32_t*)d_bfrag[m];
    for (int idx = threadIdx.x; idx < 8192; idx += blockDim.x) {
        int r = idx & 1, lane = (idx >> 1) & 31, j = (idx >> 6) & 15, ks = idx >> 10;
        int fidx = idx >> 1;
        int n = j * 8 + (lane >> 2);
        int k = ks * 16 + (lane & 3) * 2 + r * 8;
        float w0 = src[k * HIDD + n];
        float w1 = src[(k + 1) * HIDD + n];
        __half h0 = __float2half_rn(w0);
        __half h1 = __float2half_rn(w1);
        float l0f = w0 - __half2float(h0);
        float l1f = w1 - __half2float(h1);
        union { __half b[2]; uint32_t u; } uh;
        uh.b[0] = h0; uh.b[1] = h1;
        dst[fidx * 4 + r] = uh.u;                     // hi at .x/.y
        dst[fidx * 4 + 2 + r] = pack_half2(l0f, l1f); // lo at .z/.w
    }
}

// ---------------- embedding (fp16 x, fp32 pre-relu init) ----------------
struct EmbedArgs {
    const float* feat[4];
    const float* W[6];
    const float* b[6];
    const int*   times;
};

__global__ void k_embed(EmbedArgs ea) {
    __shared__ float sf[64][8];
    int t = blockIdx.y;
    int tid = threadIdx.x;
    int base = blockIdx.x * 64;
    const int FDs[6] = {4,4,4,3,0,0};
    const int Ds[6]  = {8,8,8,7,4,4};
    int FD = FDs[t], D = Ds[t];
    if (tid < 64) {
        int n = base + tid;
        if (n < NN) {
            float p = (float)ea.times[(size_t)t * NN + n];
            const float div1 = 0.01f;            // 10000^(-2/4)
            float p1 = p * div1;
            for (int dd = 0; dd < FD; ++dd) sf[tid][dd] = ea.feat[t][(size_t)n * FD + dd];
            sf[tid][FD + 0] = sinf(p);
            sf[tid][FD + 1] = cosf(p);
            sf[tid][FD + 2] = sinf(p1);
            sf[tid][FD + 3] = cosf(p1);
            for (int dd = D; dd < 8; ++dd) sf[tid][dd] = 0.f;
        }
    }
    __syncthreads();
    int j = tid;                                  // 0..127
    float Wj[8];
    float bj = ea.b[t][j];
    for (int dd = 0; dd < 8; ++dd) Wj[dd] = (dd < D) ? ea.W[t][dd * HIDD + j] : 0.f;
    int nmax = NN - base; if (nmax > 64) nmax = 64;
    for (int u = 0; u < nmax; ++u) {
        int n = base + u;
        float h = bj;
        #pragma unroll
        for (int dd = 0; dd < 8; ++dd) h += sf[u][dd] * Wj[dd];
        d_xh[0][t][(size_t)n * HIDD + j] = __float2half_rn(fmaxf(h, 0.f));
        if (t < 4) d_init[t][(size_t)n * HIDD + j] = h;
    }
}

// ---------------- degree + CSR build ----------------
__global__ void k_zero() {
    int idx = blockIdx.x * blockDim.x + threadIdx.x;
    if (idx < GG * HIDD) d_g[idx] = 0.f;
    if (idx < 24 * NN)  (&d_deg[0][0])[idx] = 0;
}

__global__ void k_deg(const int* __restrict__ edges) {
    int e = blockIdx.x * blockDim.x + threadIdx.x;
    int i = blockIdx.y;
    if (e < EE) {
        int d = edges[(size_t)i * 2 * EE + EE + e];
        atomicAdd(&d_deg[i][d], 1);
    }
}

__global__ void k_rdeg() {
    int idx = blockIdx.x * blockDim.x + threadIdx.x;
    if (idx < 24 * NN) {
        int dg = (&d_deg[0][0])[idx];
        (&d_rdeg[0][0])[idx] = 1.0f / (float)(dg > 1 ? dg : 1);
    }
}

__global__ void k_scan1() {
    __shared__ int sh[1024];
    int i = blockIdx.y;
    int d = blockIdx.x * 1024 + threadIdx.x;
    int v = (d < NN) ? d_deg[i][d] : 0;
    sh[threadIdx.x] = v;
    __syncthreads();
    #pragma unroll
    for (int off = 1; off < 1024; off <<= 1) {
        int x2 = (threadIdx.x >= off) ? sh[threadIdx.x - off] : 0;
        __syncthreads();
        sh[threadIdx.x] += x2;
        __syncthreads();
    }
    if (d < NN) d_off[i][d] = sh[threadIdx.x];      // inclusive (temp)
    if (threadIdx.x == 1023) d_bsum[i][blockIdx.x] = sh[1023];
}

__global__ void k_scan2() {
    int i = blockIdx.x;
    if (threadIdx.x == 0) {
        int run = 0;
        for (int b = 0; b < 98; b++) {
            int v = d_bsum[i][b];
            d_bsum[i][b] = run;
            run += v;
        }
    }
}

__global__ void k_scan3() {
    int i = blockIdx.y;
    int d = blockIdx.x * 1024 + threadIdx.x;
    if (d < NN) {
        int excl = d_off[i][d] - d_deg[i][d] + d_bsum[i][blockIdx.x];
        d_off[i][d] = excl;
        d_cur[i][d] = excl;
    }
    if (blockIdx.x == 0 && threadIdx.x == 0) d_off[i][NN] = EE;
}

__global__ void k_fill(const int* __restrict__ edges) {
    int e = blockIdx.x * blockDim.x + threadIdx.x;
    int i = blockIdx.y;
    if (e < EE) {
        const int* eb = edges + (size_t)i * 2 * EE;
        int s = eb[e];
        int d = eb[EE + e];
        int pos = atomicAdd(&d_cur[i][d], 1);
        d_csr_src[i][pos] = s;
    }
}

// ---------------- aggregate: agg_i[d] = rdeg_i[d] * sum_e xh[pin][src_t][s]  (fp16) ----------------
__global__ __launch_bounds__(256)
void k_gather(int pin) {
    int i = blockIdx.y;
    int w = threadIdx.x >> 5, lane = threadIdx.x & 31;
    int d = blockIdx.x * 8 + w;
    if (d >= NN) return;

    int st = __ldg(&d_off[i][d]);
    int en = __ldg(&d_off[i][d + 1]);
    float4 s4 = make_float4(0.f, 0.f, 0.f, 0.f);
    const int* srcs = d_csr_src[i];
    const uint2* xb = (const uint2*)d_xh[pin][c_src[i]];   // 4 fp16 per lane
    int e = st;
    for (; e + 7 < en; e += 8) {
        int sids[8];
        #pragma unroll
        for (int z = 0; z < 8; z++) sids[z] = __ldg(srcs + e + z);
        uint2 uv[8];
        #pragma unroll
        for (int z = 0; z < 8; z++) uv[z] = __ldg(xb + (size_t)sids[z] * 32 + lane);
        #pragma unroll
        for (int z = 0; z < 8; z++) {
            float2 f0 = __half22float2(*(__half2*)&uv[z].x);
            float2 f1 = __half22float2(*(__half2*)&uv[z].y);
            s4.x += f0.x; s4.y += f0.y; s4.z += f1.x; s4.w += f1.y;
        }
    }
    for (; e < en; e++) {
        int s0 = __ldg(srcs + e);
        uint2 u = __ldg(xb + (size_t)s0 * 32 + lane);
        float2 f0 = __half22float2(*(__half2*)&u.x);
        float2 f1 = __half22float2(*(__half2*)&u.y);
        s4.x += f0.x; s4.y += f0.y; s4.z += f1.x; s4.w += f1.y;
    }
    float rd = __ldg(&d_rdeg[i][d]);
    uint2 o;
    o.x = pack_half2(s4.x * rd, s4.y * rd);
    o.y = pack_half2(s4.z * rd, s4.w * rd);
    ((uint2*)d_agg[i])[(size_t)d * 32 + lane] = o;
}

// ---------------- fused GEMM: x[pout][t] = relu( sum_i agg_i@Wl_i + x[t]@WrSum + blsum ) ----------------
#define ASTRIDE 136
#define SMEM_TOTAL 34816

__global__ __launch_bounds__(256, 2)
void k_gemm_mma(int layer, int pin, int pout) {
    extern __shared__ char smem[];
    uint32_t sb = smem_u32(smem);
    int tid = threadIdx.x, wid = tid >> 5, l = tid & 31;
    int t = blockIdx.y;
    int r0 = blockIdx.x * 128;
    int cnt = c_dstcnt[t];
    int wr = wid & 3, wc = wid >> 2;

    float acc[2][8][4];
    #pragma unroll
    for (int mt = 0; mt < 2; mt++)
        #pragma unroll
        for (int j = 0; j < 8; j++)
            #pragma unroll
            for (int r = 0; r < 4; r++) acc[mt][j][r] = 0.f;

    #pragma unroll 1
    for (int g = 0; g <= cnt; g++) {
        const __half* Asrc;
        int mat;
        if (g < cnt) {
            int i = c_dstedges[t][g];
            Asrc = d_agg[i];
            mat = layer * 24 + i;
        } else {
            Asrc = d_xh[pin][t];
            mat = 72 + layer * 6 + t;
        }

        // ---- A tile: fp16 direct copy into padded smem ----
        const uint4* As = (const uint4*)Asrc;
        #pragma unroll
        for (int q = 0; q < 8; q++) {
            int idx = tid + q * 256;          // 2048 = 128 rows x 16 uint4
            int row = idx >> 4, c = idx & 15;
            uint4 v = make_uint4(0u, 0u, 0u, 0u);
            int gr = r0 + row;
            if (gr < NN) v = __ldg(As + (size_t)gr * 16 + c);
            *(uint4*)(smem + (size_t)(row * ASTRIDE + c * 8) * 2) = v;
        }
        __syncthreads();

        const uint4* Bf = d_bfrag[mat];
        #pragma unroll
        for (int ks = 0; ks < 8; ks++) {
            uint32_t ah[2][4];
            #pragma unroll
            for (int mt = 0; mt < 2; mt++) {
                uint32_t off = (uint32_t)(((wr * 32 + mt * 16 + (l & 15)) * ASTRIDE
                                           + ks * 16 + (l >> 4) * 8) * 2);
                asm volatile("ldmatrix.sync.aligned.m8n8.x4.shared.b16 {%0,%1,%2,%3}, [%4];"
                    : "=r"(ah[mt][0]), "=r"(ah[mt][1]), "=r"(ah[mt][2]), "=r"(ah[mt][3])
                    : "r"(sb + off));
            }
            #pragma unroll
            for (int j = 0; j < 8; j++) {
                int fidx = (ks * 16 + wc * 8 + j) * 32 + l;
                uint4 b = __ldg(Bf + fidx);   // {hi.x, hi.y, lo.x, lo.y}
                #pragma unroll
                for (int mt = 0; mt < 2; mt++) {
                    float* c = acc[mt][j];
                    asm volatile("mma.sync.aligned.m16n8k16.row.col.f32.f16.f16.f32 "
                        "{%0,%1,%2,%3}, {%4,%5,%6,%7}, {%8,%9}, {%0,%1,%2,%3};"
                        : "+f"(c[0]), "+f"(c[1]), "+f"(c[2]), "+f"(c[3])
                        : "r"(ah[mt][0]), "r"(ah[mt][1]), "r"(ah[mt][2]), "r"(ah[mt][3]),
                          "r"(b.x), "r"(b.y));
                    asm volatile("mma.sync.aligned.m16n8k16.row.col.f32.f16.f16.f32 "
                        "{%0,%1,%2,%3}, {%4,%5,%6,%7}, {%8,%9}, {%0,%1,%2,%3};"
                        : "+f"(c[0]), "+f"(c[1]), "+f"(c[2]), "+f"(c[3])
                        : "r"(ah[mt][0]), "r"(ah[mt][1]), "r"(ah[mt][2]), "r"(ah[mt][3]),
                          "r"(b.z), "r"(b.w));
                }
            }
        }
        __syncthreads();
    }

    // ---- single epilogue: bias + relu + fp16 store ----
    __half* X = d_xh[pout][t];
    const float* bias = d_blsum[layer][t];
    #pragma unroll
    for (int mt = 0; mt < 2; mt++) {
        int gr = r0 + wr * 32 + mt * 16 + (l >> 2);
        #pragma unroll
        for (int j = 0; j < 8; j++) {
            int tcol = wc * 64 + j * 8 + (l & 3) * 2;
            float b0 = bias[tcol], b1 = bias[tcol + 1];
            float* c = acc[mt][j];
            if (gr < NN)
                ((uint32_t*)(X + (size_t)gr * HIDD))[tcol >> 1] =
                    pack_half2(fmaxf(c[0] + b0, 0.f), fmaxf(c[1] + b1, 0.f));
            if (gr + 8 < NN)
                ((uint32_t*)(X + (size_t)(gr + 8) * HIDD))[tcol >> 1] =
                    pack_half2(fmaxf(c[2] + b0, 0.f), fmaxf(c[3] + b1, 0.f));
        }
    }
}

// ---------------- readout: warp per node, vectorized reduction into g ----------------
__global__ void k_gpp(int pfin, const int* __restrict__ batch) {
    int gw = (blockIdx.x * blockDim.x + threadIdx.x) >> 5;   // node slot 0..6*NN-1
    if (gw >= 6 * NN) return;
    int lane = threadIdx.x & 31;
    int t = gw / NN, n = gw - t * NN;
    float4 v;
    if (t < 4) {
        v = *(const float4*)(d_init[t] + (size_t)n * HIDD + lane * 4);
    } else {
        uint2 u = __ldg((const uint2*)d_xh[pfin][t] + (size_t)n * 32 + lane);
        float2 f0 = __half22float2(*(__half2*)&u.x);
        float2 f1 = __half22float2(*(__half2*)&u.y);
        v = make_float4(f0.x, f0.y, f1.x, f1.y);
    }
    int bg = __ldg(batch + (size_t)t * NN + n);
    float* op = d_g + (size_t)bg * HIDD + lane * 4;
    asm volatile("red.global.add.v4.f32 [%0], {%1,%2,%3,%4};"
                 :: "l"(op), "f"(v.x), "f"(v.y), "f"(v.z), "f"(v.w) : "memory");
}

// ---------------- graph MLP head ----------------
__global__ void k_mlp(float* __restrict__ out,
                      const float* __restrict__ W1, const float* __restrict__ b1,
                      const float* __restrict__ W2, const float* __restrict__ b2) {
    __shared__ float s[4][HIDD];
    int warp = threadIdx.x >> 5, lane = threadIdx.x & 31;
    int gidx = blockIdx.x * 4 + warp;
    if (gidx >= GG) return;
    #pragma unroll
    for (int q = 0; q < 4; q++) {
        float v = d_g[(size_t)gidx * HIDD + lane + q * 32];
        s[warp][lane + q * 32] = fmaxf(v, 0.f);
    }
    __syncwarp();
    float h = b1[lane];
    #pragma unroll 8
    for (int k = 0; k < HIDD; k++) h += s[warp][k] * W1[k * 32 + lane];
    h = fmaxf(h, 0.f);
    float val = h * W2[lane];
    #pragma unroll
    for (int off = 16; off; off >>= 1) val += __shfl_xor_sync(0xffffffffu, val, off);
    if (lane == 0) out[gidx] = val + b2[0];
}

// ---------------- launch ----------------
extern "C" void kernel_launch(void* const* d_in, const int* in_sizes, int n_in,
                              void* d_out, int out_size) {
    const float* Wl   = (const float*)d_in[16];
    const float* bl   = (const float*)d_in[17];
    const float* Wr   = (const float*)d_in[18];
    const float* W1   = (const float*)d_in[19];
    const float* b1   = (const float*)d_in[20];
    const float* W2   = (const float*)d_in[21];
    const float* b2   = (const float*)d_in[22];
    const int* times  = (const int*)d_in[23];
    const int* edges  = (const int*)d_in[24];
    const int* batch  = (const int*)d_in[25];

    cudaFuncSetAttribute(k_gemm_mma, cudaFuncAttributeMaxDynamicSharedMemorySize, SMEM_TOTAL);

    k_zero<<<9375, 256>>>();
    k_deg<<<dim3(391, 24), 1024>>>(edges);
    k_rdeg<<<9375, 256>>>();
    k_scan1<<<dim3(98, 24), 1024>>>();
    k_scan2<<<24, 32>>>();
    k_scan3<<<dim3(98, 24), 1024>>>();
    k_fill<<<dim3(391, 24), 1024>>>(edges);

    k_wrsum<<<18, 256>>>(Wr, bl);
    k_wprep<<<90, 256>>>(Wl);

    EmbedArgs ea;
    for (int t = 0; t < 4; t++) ea.feat[t] = (const float*)d_in[t];
    for (int t = 0; t < 6; t++) {
        ea.W[t] = (const float*)d_in[4 + 2 * t];
        ea.b[t] = (const float*)d_in[5 + 2 * t];
    }
    ea.times = times;
    k_embed<<<dim3(1563, 6), 128>>>(ea);

    int pin = 0;
    for (int layer = 0; layer < 3; ++layer) {
        int pout = pin ^ 1;
        k_gather<<<dim3(12500, 24), 256>>>(pin);
        k_gemm_mma<<<dim3(782, 6), 256, SMEM_TOTAL>>>(layer, pin, pout);
        pin = pout;
    }

    k_gpp<<<75000, 256>>>(pin, batch);
    k_mlp<<<128, 128>>>((float*)d_out, W1, b1, W2, b2);
}

// round 16
// speedup vs baseline: 1.4872x; 1.0033x over previous
#include <cuda_runtime.h>
#include <cuda_fp16.h>
#include <cstdint>
#include <cstddef>

#define NN   100000
#define HIDD 128
#define EE   400000
#define GG   512

// ---------------- device scratch (static, no allocations) ----------------
__device__ __half d_xh[2][6][NN * HIDD];          // ping-pong node features (fp16, post-relu)
__device__ __half d_agg[24][NN * HIDD];           // per-edge-type aggregated means (fp16)
__device__ float d_init[4][NN * HIDD];            // pre-relu embed (readout contribution)
__device__ float d_g[GG * HIDD];                  // graph readout accumulator
__device__ int   d_deg[24][NN];
__device__ float d_rdeg[24][NN];
__device__ int   d_off[24][NN + 1];               // CSR offsets (by dst)
__device__ int   d_cur[24][NN];                   // fill cursors
__device__ int   d_csr_src[24][EE];               // src ids sorted by dst
__device__ int   d_bsum[24][128];                 // scan block sums
__device__ float d_wrsum[3][6][HIDD * HIDD];      // sum of Wr over edge types with dst=t
__device__ float d_blsum[3][6][HIDD];             // sum of bl over edge types with dst=t
// split-fp16 weights (hi+lo ~22 bits), m16n8k16 B-frag order, interleaved {hi.x,hi.y,lo.x,lo.y}
__device__ uint4 d_bfrag[90][4096];

// ---------------- edge-type tables ----------------
// type ids: 0 ssBox, 1 place_frame, 2 object, 3 ssCylinder, 4 pick, 5 place
__constant__ int c_src[24] = {2,0,1,0,1,2,4,5,2,0,1,3,2,4,1,4,3,4,2,5,3,5,1,5};
__constant__ int c_dstcnt[6] = {3,5,5,3,4,4};
__constant__ int c_dstedges[6][5] = {
    {0,2,9,-1,-1},{3,5,10,15,23},{1,4,8,13,19},{11,17,21,-1,-1},{7,12,14,16,-1},{6,18,20,22,-1}};

__device__ __forceinline__ uint32_t smem_u32(const void* p) {
    uint32_t a;
    asm("{ .reg .u64 t; cvta.to.shared.u64 t, %1; cvt.u32.u64 %0, t; }" : "=r"(a) : "l"(p));
    return a;
}
__device__ __forceinline__ uint32_t pack_half2(float a, float b) {
    union { __half2 h; uint32_t u; } v;
    v.h = __floats2half2_rn(a, b);           // a -> low half, b -> high
    return v.u;
}

// ---------------- prep kernels ----------------
__global__ void k_wrsum(const float* __restrict__ Wr, const float* __restrict__ bl) {
    int bid = blockIdx.x;               // 0..17
    int layer = bid / 6, t = bid % 6;
    int cnt = c_dstcnt[t];
    for (int e = threadIdx.x; e < HIDD * HIDD; e += blockDim.x) {
        float sv = 0.f;
        for (int q = 0; q < cnt; q++) {
            int i = c_dstedges[t][q];
            sv += Wr[(size_t)(layer * 24 + i) * HIDD * HIDD + e];
        }
        d_wrsum[layer][t][e] = sv;
    }
    if (threadIdx.x < HIDD) {
        float sv = 0.f;
        for (int q = 0; q < cnt; q++) {
            int i = c_dstedges[t][q];
            sv += bl[(size_t)(layer * 24 + i) * HIDD + threadIdx.x];
        }
        d_blsum[layer][t][threadIdx.x] = sv;
    }
}

// weight prep: split-fp16 (hi = fp16(w), lo = fp16(w - hi)), m16n8k16 B-fragment order
__global__ void k_wprep(const float* __restrict__ Wl) {
    int m = blockIdx.x;                 // 0..89: 0..71 = Wl[layer*24+i], 72..89 = wrsum
    const float* src = (m < 72) ? (Wl + (size_t)m * HIDD * HIDD)
                                : (&d_wrsum[0][0][0] + (size_t)(m - 72) * HIDD * HIDD);
    uint32_t* dst = (uint32_t*)d_bfrag[m];
    for (int idx = threadIdx.x; idx < 8192; idx += blockDim.x) {
        int r = idx & 1, lane = (idx >> 1) & 31, j = (idx >> 6) & 15, ks = idx >> 10;
        int fidx = idx >> 1;
        int n = j * 8 + (lane >> 2);
        int k = ks * 16 + (lane & 3) * 2 + r * 8;
        float w0 = src[k * HIDD + n];
        float w1 = src[(k + 1) * HIDD + n];
        __half h0 = __float2half_rn(w0);
        __half h1 = __float2half_rn(w1);
        float l0f = w0 - __half2float(h0);
        float l1f = w1 - __half2float(h1);
        union { __half b[2]; uint32_t u; } uh;
        uh.b[0] = h0; uh.b[1] = h1;
        dst[fidx * 4 + r] = uh.u;                     // hi at .x/.y
        dst[fidx * 4 + 2 + r] = pack_half2(l0f, l1f); // lo at .z/.w
    }
}

// ---------------- embedding (fp16 x, fp32 pre-relu init) ----------------
struct EmbedArgs {
    const float* feat[4];
    const float* W[6];
    const float* b[6];
    const int*   times;
};

__global__ void k_embed(EmbedArgs ea) {
    __shared__ float sf[64][8];
    int t = blockIdx.y;
    int tid = threadIdx.x;
    int base = blockIdx.x * 64;
    const int FDs[6] = {4,4,4,3,0,0};
    const int Ds[6]  = {8,8,8,7,4,4};
    int FD = FDs[t], D = Ds[t];
    if (tid < 64) {
        int n = base + tid;
        if (n < NN) {
            float p = (float)ea.times[(size_t)t * NN + n];
            const float div1 = 0.01f;            // 10000^(-2/4)
            float p1 = p * div1;
            for (int dd = 0; dd < FD; ++dd) sf[tid][dd] = ea.feat[t][(size_t)n * FD + dd];
            sf[tid][FD + 0] = sinf(p);
            sf[tid][FD + 1] = cosf(p);
            sf[tid][FD + 2] = sinf(p1);
            sf[tid][FD + 3] = cosf(p1);
            for (int dd = D; dd < 8; ++dd) sf[tid][dd] = 0.f;
        }
    }
    __syncthreads();
    int j = tid;                                  // 0..127
    float Wj[8];
    float bj = ea.b[t][j];
    for (int dd = 0; dd < 8; ++dd) Wj[dd] = (dd < D) ? ea.W[t][dd * HIDD + j] : 0.f;
    int nmax = NN - base; if (nmax > 64) nmax = 64;
    for (int u = 0; u < nmax; ++u) {
        int n = base + u;
        float h = bj;
        #pragma unroll
        for (int dd = 0; dd < 8; ++dd) h += sf[u][dd] * Wj[dd];
        d_xh[0][t][(size_t)n * HIDD + j] = __float2half_rn(fmaxf(h, 0.f));
        if (t < 4) d_init[t][(size_t)n * HIDD + j] = h;
    }
}

// ---------------- degree + CSR build ----------------
__global__ void k_zero() {
    int idx = blockIdx.x * blockDim.x + threadIdx.x;
    if (idx < GG * HIDD) d_g[idx] = 0.f;
    if (idx < 24 * NN)  (&d_deg[0][0])[idx] = 0;
}

__global__ void k_deg(const int* __restrict__ edges) {
    int e = blockIdx.x * blockDim.x + threadIdx.x;
    int i = blockIdx.y;
    if (e < EE) {
        int d = edges[(size_t)i * 2 * EE + EE + e];
        atomicAdd(&d_deg[i][d], 1);
    }
}

__global__ void k_scan1() {
    __shared__ int sh[1024];
    int i = blockIdx.y;
    int d = blockIdx.x * 1024 + threadIdx.x;
    int v = (d < NN) ? d_deg[i][d] : 0;
    sh[threadIdx.x] = v;
    __syncthreads();
    #pragma unroll
    for (int off = 1; off < 1024; off <<= 1) {
        int x2 = (threadIdx.x >= off) ? sh[threadIdx.x - off] : 0;
        __syncthreads();
        sh[threadIdx.x] += x2;
        __syncthreads();
    }
    if (d < NN) d_off[i][d] = sh[threadIdx.x];      // inclusive (temp)
    if (threadIdx.x == 1023) d_bsum[i][blockIdx.x] = sh[1023];
}

__global__ void k_scan2() {
    int i = blockIdx.x;
    if (threadIdx.x == 0) {
        int run = 0;
        for (int b = 0; b < 98; b++) {
            int v = d_bsum[i][b];
            d_bsum[i][b] = run;
            run += v;
        }
    }
}

__global__ void k_scan3() {
    int i = blockIdx.y;
    int d = blockIdx.x * 1024 + threadIdx.x;
    if (d < NN) {
        int dg = d_deg[i][d];
        int excl = d_off[i][d] - dg + d_bsum[i][blockIdx.x];
        d_off[i][d] = excl;
        d_cur[i][d] = excl;
        d_rdeg[i][d] = 1.0f / (float)(dg > 1 ? dg : 1);   // fused rdeg
    }
    if (blockIdx.x == 0 && threadIdx.x == 0) d_off[i][NN] = EE;
}

__global__ void k_fill(const int* __restrict__ edges) {
    int e = blockIdx.x * blockDim.x + threadIdx.x;
    int i = blockIdx.y;
    if (e < EE) {
        const int* eb = edges + (size_t)i * 2 * EE;
        int s = eb[e];
        int d = eb[EE + e];
        int pos = atomicAdd(&d_cur[i][d], 1);
        d_csr_src[i][pos] = s;
    }
}

// ---------------- aggregate: agg_i[d] = rdeg_i[d] * sum_e xh[pin][src_t][s]  (fp16) ----------------
// 8-edge unroll; adjacent edge pairs combined in fp16 (hadd2) before fp32 accumulation.
__global__ __launch_bounds__(256)
void k_gather(int pin) {
    int i = blockIdx.y;
    int w = threadIdx.x >> 5, lane = threadIdx.x & 31;
    int d = blockIdx.x * 8 + w;
    if (d >= NN) return;

    int st = __ldg(&d_off[i][d]);
    int en = __ldg(&d_off[i][d + 1]);
    float4 s4 = make_float4(0.f, 0.f, 0.f, 0.f);
    const int* srcs = d_csr_src[i];
    const uint2* xb = (const uint2*)d_xh[pin][c_src[i]];   // 4 fp16 per lane
    int e = st;
    for (; e + 7 < en; e += 8) {
        int sids[8];
        #pragma unroll
        for (int z = 0; z < 8; z++) sids[z] = __ldg(srcs + e + z);
        uint2 uv[8];
        #pragma unroll
        for (int z = 0; z < 8; z++) uv[z] = __ldg(xb + (size_t)sids[z] * 32 + lane);
        #pragma unroll
        for (int z = 0; z < 4; z++) {
            __half2 pa = __hadd2(*(__half2*)&uv[2 * z].x, *(__half2*)&uv[2 * z + 1].x);
            __half2 pb = __hadd2(*(__half2*)&uv[2 * z].y, *(__half2*)&uv[2 * z + 1].y);
            float2 f0 = __half22float2(pa);
            float2 f1 = __half22float2(pb);
            s4.x += f0.x; s4.y += f0.y; s4.z += f1.x; s4.w += f1.y;
        }
    }
    for (; e < en; e++) {
        int s0 = __ldg(srcs + e);
        uint2 u = __ldg(xb + (size_t)s0 * 32 + lane);
        float2 f0 = __half22float2(*(__half2*)&u.x);
        float2 f1 = __half22float2(*(__half2*)&u.y);
        s4.x += f0.x; s4.y += f0.y; s4.z += f1.x; s4.w += f1.y;
    }
    float rd = __ldg(&d_rdeg[i][d]);
    uint2 o;
    o.x = pack_half2(s4.x * rd, s4.y * rd);
    o.y = pack_half2(s4.z * rd, s4.w * rd);
    ((uint2*)d_agg[i])[(size_t)d * 32 + lane] = o;
}

// ---------------- fused GEMM: x[pout][t] = relu( sum_i agg_i@Wl_i + x[t]@WrSum + blsum ) ----------------
#define ASTRIDE 136
#define SMEM_TOTAL 34816

__global__ __launch_bounds__(256, 2)
void k_gemm_mma(int layer, int pin, int pout) {
    extern __shared__ char smem[];
    uint32_t sb = smem_u32(smem);
    int tid = threadIdx.x, wid = tid >> 5, l = tid & 31;
    int t = blockIdx.y;
    int r0 = blockIdx.x * 128;
    int cnt = c_dstcnt[t];
    int wr = wid & 3, wc = wid >> 2;

    float acc[2][8][4];
    #pragma unroll
    for (int mt = 0; mt < 2; mt++)
        #pragma unroll
        for (int j = 0; j < 8; j++)
            #pragma unroll
            for (int r = 0; r < 4; r++) acc[mt][j][r] = 0.f;

    #pragma unroll 1
    for (int g = 0; g <= cnt; g++) {
        const __half* Asrc;
        int mat;
        if (g < cnt) {
            int i = c_dstedges[t][g];
            Asrc = d_agg[i];
            mat = layer * 24 + i;
        } else {
            Asrc = d_xh[pin][t];
            mat = 72 + layer * 6 + t;
        }

        // ---- A tile: fp16 direct copy into padded smem ----
        const uint4* As = (const uint4*)Asrc;
        #pragma unroll
        for (int q = 0; q < 8; q++) {
            int idx = tid + q * 256;          // 2048 = 128 rows x 16 uint4
            int row = idx >> 4, c = idx & 15;
            uint4 v = make_uint4(0u, 0u, 0u, 0u);
            int gr = r0 + row;
            if (gr < NN) v = __ldg(As + (size_t)gr * 16 + c);
            *(uint4*)(smem + (size_t)(row * ASTRIDE + c * 8) * 2) = v;
        }
        __syncthreads();

        const uint4* Bf = d_bfrag[mat];
        #pragma unroll
        for (int ks = 0; ks < 8; ks++) {
            uint32_t ah[2][4];
            #pragma unroll
            for (int mt = 0; mt < 2; mt++) {
                uint32_t off = (uint32_t)(((wr * 32 + mt * 16 + (l & 15)) * ASTRIDE
                                           + ks * 16 + (l >> 4) * 8) * 2);
                asm volatile("ldmatrix.sync.aligned.m8n8.x4.shared.b16 {%0,%1,%2,%3}, [%4];"
                    : "=r"(ah[mt][0]), "=r"(ah[mt][1]), "=r"(ah[mt][2]), "=r"(ah[mt][3])
                    : "r"(sb + off));
            }
            #pragma unroll
            for (int j = 0; j < 8; j++) {
                int fidx = (ks * 16 + wc * 8 + j) * 32 + l;
                uint4 b = __ldg(Bf + fidx);   // {hi.x, hi.y, lo.x, lo.y}
                #pragma unroll
                for (int mt = 0; mt < 2; mt++) {
                    float* c = acc[mt][j];
                    asm volatile("mma.sync.aligned.m16n8k16.row.col.f32.f16.f16.f32 "
                        "{%0,%1,%2,%3}, {%4,%5,%6,%7}, {%8,%9}, {%0,%1,%2,%3};"
                        : "+f"(c[0]), "+f"(c[1]), "+f"(c[2]), "+f"(c[3])
                        : "r"(ah[mt][0]), "r"(ah[mt][1]), "r"(ah[mt][2]), "r"(ah[mt][3]),
                          "r"(b.x), "r"(b.y));
                    asm volatile("mma.sync.aligned.m16n8k16.row.col.f32.f16.f16.f32 "
                        "{%0,%1,%2,%3}, {%4,%5,%6,%7}, {%8,%9}, {%0,%1,%2,%3};"
                        : "+f"(c[0]), "+f"(c[1]), "+f"(c[2]), "+f"(c[3])
                        : "r"(ah[mt][0]), "r"(ah[mt][1]), "r"(ah[mt][2]), "r"(ah[mt][3]),
                          "r"(b.z), "r"(b.w));
                }
            }
        }
        __syncthreads();
    }

    // ---- single epilogue: bias + relu + fp16 store ----
    __half* X = d_xh[pout][t];
    const float* bias = d_blsum[layer][t];
    #pragma unroll
    for (int mt = 0; mt < 2; mt++) {
        int gr = r0 + wr * 32 + mt * 16 + (l >> 2);
        #pragma unroll
        for (int j = 0; j < 8; j++) {
            int tcol = wc * 64 + j * 8 + (l & 3) * 2;
            float b0 = bias[tcol], b1 = bias[tcol + 1];
            float* c = acc[mt][j];
            if (gr < NN)
                ((uint32_t*)(X + (size_t)gr * HIDD))[tcol >> 1] =
                    pack_half2(fmaxf(c[0] + b0, 0.f), fmaxf(c[1] + b1, 0.f));
            if (gr + 8 < NN)
                ((uint32_t*)(X + (size_t)(gr + 8) * HIDD))[tcol >> 1] =
                    pack_half2(fmaxf(c[2] + b0, 0.f), fmaxf(c[3] + b1, 0.f));
        }
    }
}

// ---------------- readout: warp per node, vectorized reduction into g ----------------
__global__ void k_gpp(int pfin, const int* __restrict__ batch) {
    int gw = (blockIdx.x * blockDim.x + threadIdx.x) >> 5;   // node slot 0..6*NN-1
    if (gw >= 6 * NN) return;
    int lane = threadIdx.x & 31;
    int t = gw / NN, n = gw - t * NN;
    float4 v;
    if (t < 4) {
        v = *(const float4*)(d_init[t] + (size_t)n * HIDD + lane * 4);
    } else {
        uint2 u = __ldg((const uint2*)d_xh[pfin][t] + (size_t)n * 32 + lane);
        float2 f0 = __half22float2(*(__half2*)&u.x);
        float2 f1 = __half22float2(*(__half2*)&u.y);
        v = make_float4(f0.x, f0.y, f1.x, f1.y);
    }
    int bg = __ldg(batch + (size_t)t * NN + n);
    float* op = d_g + (size_t)bg * HIDD + lane * 4;
    asm volatile("red.global.add.v4.f32 [%0], {%1,%2,%3,%4};"
                 :: "l"(op), "f"(v.x), "f"(v.y), "f"(v.z), "f"(v.w) : "memory");
}

// ---------------- graph MLP head ----------------
__global__ void k_mlp(float* __restrict__ out,
                      const float* __restrict__ W1, const float* __restrict__ b1,
                      const float* __restrict__ W2, const float* __restrict__ b2) {
    __shared__ float s[4][HIDD];
    int warp = threadIdx.x >> 5, lane = threadIdx.x & 31;
    int gidx = blockIdx.x * 4 + warp;
    if (gidx >= GG) return;
    #pragma unroll
    for (int q = 0; q < 4; q++) {
        float v = d_g[(size_t)gidx * HIDD + lane + q * 32];
        s[warp][lane + q * 32] = fmaxf(v, 0.f);
    }
    __syncwarp();
    float h = b1[lane];
    #pragma unroll 8
    for (int k = 0; k < HIDD; k++) h += s[warp][k] * W1[k * 32 + lane];
    h = fmaxf(h, 0.f);
    float val = h * W2[lane];
    #pragma unroll
    for (int off = 16; off; off >>= 1) val += __shfl_xor_sync(0xffffffffu, val, off);
    if (lane == 0) out[gidx] = val + b2[0];
}

// ---------------- launch ----------------
extern "C" void kernel_launch(void* const* d_in, const int* in_sizes, int n_in,
                              void* d_out, int out_size) {
    const float* Wl   = (const float*)d_in[16];
    const float* bl   = (const float*)d_in[17];
    const float* Wr   = (const float*)d_in[18];
    const float* W1   = (const float*)d_in[19];
    const float* b1   = (const float*)d_in[20];
    const float* W2   = (const float*)d_in[21];
    const float* b2   = (const float*)d_in[22];
    const int* times  = (const int*)d_in[23];
    const int* edges  = (const int*)d_in[24];
    const int* batch  = (const int*)d_in[25];

    cudaFuncSetAttribute(k_gemm_mma, cudaFuncAttributeMaxDynamicSharedMemorySize, SMEM_TOTAL);

    k_zero<<<9375, 256>>>();
    k_deg<<<dim3(391, 24), 1024>>>(edges);
    k_scan1<<<dim3(98, 24), 1024>>>();
    k_scan2<<<24, 32>>>();
    k_scan3<<<dim3(98, 24), 1024>>>();
    k_fill<<<dim3(391, 24), 1024>>>(edges);

    k_wrsum<<<18, 256>>>(Wr, bl);
    k_wprep<<<90, 256>>>(Wl);

    EmbedArgs ea;
    for (int t = 0; t < 4; t++) ea.feat[t] = (const float*)d_in[t];
    for (int t = 0; t < 6; t++) {
        ea.W[t] = (const float*)d_in[4 + 2 * t];
        ea.b[t] = (const float*)d_in[5 + 2 * t];
    }
    ea.times = times;
    k_embed<<<dim3(1563, 6), 128>>>(ea);

    int pin = 0;
    for (int layer = 0; layer < 3; ++layer) {
        int pout = pin ^ 1;
        k_gather<<<dim3(12500, 24), 256>>>(pin);
        k_gemm_mma<<<dim3(782, 6), 256, SMEM_TOTAL>>>(layer, pin, pout);
        pin = pout;
    }

    k_gpp<<<75000, 256>>>(pin, batch);
    k_mlp<<<128, 128>>>((float*)d_out, W1, b1, W2, b2);
}

// round 17
// speedup vs baseline: 1.5543x; 1.0451x over previous
#include <cuda_runtime.h>
#include <cuda_fp16.h>
#include <cstdint>
#include <cstddef>

#define NN   100000
#define HIDD 128
#define EE   400000
#define GG   512

// ---------------- device scratch (static, no allocations) ----------------
__device__ __half d_xh[2][6][NN * HIDD];          // ping-pong node features (fp16, post-relu)
__device__ __half d_agg[24][NN * HIDD];           // per-edge-type aggregated means (fp16)
__device__ float d_init[4][NN * HIDD];            // pre-relu embed (readout contribution)
__device__ float d_g[GG * HIDD];                  // graph readout accumulator
__device__ int   d_deg[24][NN];
__device__ float d_rdeg[24][NN];
__device__ int   d_off[24][NN + 1];               // CSR offsets (by dst)
__device__ int   d_cur[24][NN];                   // fill cursors
__device__ int   d_csr_src[24][EE];               // src ids sorted by dst
__device__ int   d_bsum[24][128];                 // scan block sums
__device__ float d_wrsum[3][6][HIDD * HIDD];      // sum of Wr over edge types with dst=t
__device__ float d_blsum[3][6][HIDD];             // sum of bl over edge types with dst=t
// split-fp16 weights (hi+lo ~22 bits), m16n8k16 B-frag order, interleaved {hi.x,hi.y,lo.x,lo.y}
__device__ uint4 d_bfrag[90][4096];

// ---------------- edge-type tables ----------------
// type ids: 0 ssBox, 1 place_frame, 2 object, 3 ssCylinder, 4 pick, 5 place
__constant__ int c_src[24] = {2,0,1,0,1,2,4,5,2,0,1,3,2,4,1,4,3,4,2,5,3,5,1,5};
__constant__ int c_dstcnt[6] = {3,5,5,3,4,4};
__constant__ int c_dstedges[6][5] = {
    {0,2,9,-1,-1},{3,5,10,15,23},{1,4,8,13,19},{11,17,21,-1,-1},{7,12,14,16,-1},{6,18,20,22,-1}};

__device__ __forceinline__ uint32_t smem_u32(const void* p) {
    uint32_t a;
    asm("{ .reg .u64 t; cvta.to.shared.u64 t, %1; cvt.u32.u64 %0, t; }" : "=r"(a) : "l"(p));
    return a;
}
__device__ __forceinline__ uint32_t pack_half2(float a, float b) {
    union { __half2 h; uint32_t u; } v;
    v.h = __floats2half2_rn(a, b);           // a -> low half, b -> high
    return v.u;
}

// ---------------- prep kernels ----------------
__global__ void k_wrsum(const float* __restrict__ Wr, const float* __restrict__ bl) {
    int bid = blockIdx.x;               // 0..17
    int layer = bid / 6, t = bid % 6;
    int cnt = c_dstcnt[t];
    for (int e = threadIdx.x; e < HIDD * HIDD; e += blockDim.x) {
        float sv = 0.f;
        for (int q = 0; q < cnt; q++) {
            int i = c_dstedges[t][q];
            sv += Wr[(size_t)(layer * 24 + i) * HIDD * HIDD + e];
        }
        d_wrsum[layer][t][e] = sv;
    }
    if (threadIdx.x < HIDD) {
        float sv = 0.f;
        for (int q = 0; q < cnt; q++) {
            int i = c_dstedges[t][q];
            sv += bl[(size_t)(layer * 24 + i) * HIDD + threadIdx.x];
        }
        d_blsum[layer][t][threadIdx.x] = sv;
    }
}

// weight prep: split-fp16 (hi = fp16(w), lo = fp16(w - hi)), m16n8k16 B-fragment order
__global__ void k_wprep(const float* __restrict__ Wl) {
    int m = blockIdx.x;                 // 0..89: 0..71 = Wl[layer*24+i], 72..89 = wrsum
    const float* src = (m < 72) ? (Wl + (size_t)m * HIDD * HIDD)
                                : (&d_wrsum[0][0][0] + (size_t)(m - 72) * HIDD * HIDD);
    uint32_t* dst = (uint32_t*)d_bfrag[m];
    for (int idx = threadIdx.x; idx < 8192; idx += blockDim.x) {
        int r = idx & 1, lane = (idx >> 1) & 31, j = (idx >> 6) & 15, ks = idx >> 10;
        int fidx = idx >> 1;
        int n = j * 8 + (lane >> 2);
        int k = ks * 16 + (lane & 3) * 2 + r * 8;
        float w0 = src[k * HIDD + n];
        float w1 = src[(k + 1) * HIDD + n];
        __half h0 = __float2half_rn(w0);
        __half h1 = __float2half_rn(w1);
        float l0f = w0 - __half2float(h0);
        float l1f = w1 - __half2float(h1);
        union { __half b[2]; uint32_t u; } uh;
        uh.b[0] = h0; uh.b[1] = h1;
        dst[fidx * 4 + r] = uh.u;                     // hi at .x/.y
        dst[fidx * 4 + 2 + r] = pack_half2(l0f, l1f); // lo at .z/.w
    }
}

// ---------------- embedding (fp16 x, fp32 pre-relu init) ----------------
struct EmbedArgs {
    const float* feat[4];
    const float* W[6];
    const float* b[6];
    const int*   times;
};

__global__ void k_embed(EmbedArgs ea) {
    __shared__ float sf[64][8];
    int t = blockIdx.y;
    int tid = threadIdx.x;
    int base = blockIdx.x * 64;
    const int FDs[6] = {4,4,4,3,0,0};
    const int Ds[6]  = {8,8,8,7,4,4};
    int FD = FDs[t], D = Ds[t];
    if (tid < 64) {
        int n = base + tid;
        if (n < NN) {
            float p = (float)ea.times[(size_t)t * NN + n];
            const float div1 = 0.01f;            // 10000^(-2/4)
            float p1 = p * div1;
            for (int dd = 0; dd < FD; ++dd) sf[tid][dd] = ea.feat[t][(size_t)n * FD + dd];
            sf[tid][FD + 0] = sinf(p);
            sf[tid][FD + 1] = cosf(p);
            sf[tid][FD + 2] = sinf(p1);
            sf[tid][FD + 3] = cosf(p1);
            for (int dd = D; dd < 8; ++dd) sf[tid][dd] = 0.f;
        }
    }
    __syncthreads();
    int j = tid;                                  // 0..127
    float Wj[8];
    float bj = ea.b[t][j];
    for (int dd = 0; dd < 8; ++dd) Wj[dd] = (dd < D) ? ea.W[t][dd * HIDD + j] : 0.f;
    int nmax = NN - base; if (nmax > 64) nmax = 64;
    for (int u = 0; u < nmax; ++u) {
        int n = base + u;
        float h = bj;
        #pragma unroll
        for (int dd = 0; dd < 8; ++dd) h += sf[u][dd] * Wj[dd];
        d_xh[0][t][(size_t)n * HIDD + j] = __float2half_rn(fmaxf(h, 0.f));
        if (t < 4) d_init[t][(size_t)n * HIDD + j] = h;
    }
}

// ---------------- degree + CSR build ----------------
__global__ void k_zero() {
    int idx = blockIdx.x * blockDim.x + threadIdx.x;
    if (idx < GG * HIDD) d_g[idx] = 0.f;
    if (idx < 24 * NN)  (&d_deg[0][0])[idx] = 0;
}

__global__ void k_deg(const int* __restrict__ edges) {
    int e = blockIdx.x * blockDim.x + threadIdx.x;
    int i = blockIdx.y;
    if (e < EE) {
        int d = edges[(size_t)i * 2 * EE + EE + e];
        atomicAdd(&d_deg[i][d], 1);
    }
}

__global__ void k_scan1() {
    __shared__ int sh[1024];
    int i = blockIdx.y;
    int d = blockIdx.x * 1024 + threadIdx.x;
    int v = (d < NN) ? d_deg[i][d] : 0;
    sh[threadIdx.x] = v;
    __syncthreads();
    #pragma unroll
    for (int off = 1; off < 1024; off <<= 1) {
        int x2 = (threadIdx.x >= off) ? sh[threadIdx.x - off] : 0;
        __syncthreads();
        sh[threadIdx.x] += x2;
        __syncthreads();
    }
    if (d < NN) d_off[i][d] = sh[threadIdx.x];      // inclusive (temp)
    if (threadIdx.x == 1023) d_bsum[i][blockIdx.x] = sh[1023];
}

__global__ void k_scan2() {
    int i = blockIdx.x;
    if (threadIdx.x == 0) {
        int run = 0;
        for (int b = 0; b < 98; b++) {
            int v = d_bsum[i][b];
            d_bsum[i][b] = run;
            run += v;
        }
    }
}

__global__ void k_scan3() {
    int i = blockIdx.y;
    int d = blockIdx.x * 1024 + threadIdx.x;
    if (d < NN) {
        int dg = d_deg[i][d];
        int excl = d_off[i][d] - dg + d_bsum[i][blockIdx.x];
        d_off[i][d] = excl;
        d_cur[i][d] = excl;
        d_rdeg[i][d] = 1.0f / (float)(dg > 1 ? dg : 1);   // fused rdeg
    }
    if (blockIdx.x == 0 && threadIdx.x == 0) d_off[i][NN] = EE;
}

__global__ void k_fill(const int* __restrict__ edges) {
    int e = blockIdx.x * blockDim.x + threadIdx.x;
    int i = blockIdx.y;
    if (e < EE) {
        const int* eb = edges + (size_t)i * 2 * EE;
        int s = eb[e];
        int d = eb[EE + e];
        int pos = atomicAdd(&d_cur[i][d], 1);
        d_csr_src[i][pos] = s;
    }
}

// ---------------- aggregate: agg_i[d] = rdeg_i[d] * sum_e xh[pin][src_t][s]  (fp16) ----------------
__global__ __launch_bounds__(256)
void k_gather(int pin) {
    int i = blockIdx.y;
    int w = threadIdx.x >> 5, lane = threadIdx.x & 31;
    int d = blockIdx.x * 8 + w;
    if (d >= NN) return;

    int st = __ldg(&d_off[i][d]);
    int en = __ldg(&d_off[i][d + 1]);
    float4 s4 = make_float4(0.f, 0.f, 0.f, 0.f);
    const int* srcs = d_csr_src[i];
    const uint2* xb = (const uint2*)d_xh[pin][c_src[i]];   // 4 fp16 per lane
    int e = st;
    for (; e + 7 < en; e += 8) {
        int sids[8];
        #pragma unroll
        for (int z = 0; z < 8; z++) sids[z] = __ldg(srcs + e + z);
        uint2 uv[8];
        #pragma unroll
        for (int z = 0; z < 8; z++) uv[z] = __ldg(xb + (size_t)sids[z] * 32 + lane);
        #pragma unroll
        for (int z = 0; z < 4; z++) {
            __half2 pa = __hadd2(*(__half2*)&uv[2 * z].x, *(__half2*)&uv[2 * z + 1].x);
            __half2 pb = __hadd2(*(__half2*)&uv[2 * z].y, *(__half2*)&uv[2 * z + 1].y);
            float2 f0 = __half22float2(pa);
            float2 f1 = __half22float2(pb);
            s4.x += f0.x; s4.y += f0.y; s4.z += f1.x; s4.w += f1.y;
        }
    }
    for (; e < en; e++) {
        int s0 = __ldg(srcs + e);
        uint2 u = __ldg(xb + (size_t)s0 * 32 + lane);
        float2 f0 = __half22float2(*(__half2*)&u.x);
        float2 f1 = __half22float2(*(__half2*)&u.y);
        s4.x += f0.x; s4.y += f0.y; s4.z += f1.x; s4.w += f1.y;
    }
    float rd = __ldg(&d_rdeg[i][d]);
    uint2 o;
    o.x = pack_half2(s4.x * rd, s4.y * rd);
    o.y = pack_half2(s4.z * rd, s4.w * rd);
    ((uint2*)d_agg[i])[(size_t)d * 32 + lane] = o;
}

// ---------------- fused GEMM: x[pout][t] = relu( sum_i agg_i@Wl_i + x[t]@WrSum + blsum ) ----------------
// warp grid 2x4: wr in {0,1} covers 64 rows (4 x m16), wc in {0..3} covers 32 cols (4 x n8)
#define ASTRIDE 136
#define SMEM_TOTAL 34816

__global__ __launch_bounds__(256, 2)
void k_gemm_mma(int layer, int pin, int pout) {
    extern __shared__ char smem[];
    uint32_t sb = smem_u32(smem);
    int tid = threadIdx.x, wid = tid >> 5, l = tid & 31;
    int t = blockIdx.y;
    int r0 = blockIdx.x * 128;
    int cnt = c_dstcnt[t];
    int wr = wid & 1, wc = wid >> 1;

    float acc[4][4][4];
    #pragma unroll
    for (int mt = 0; mt < 4; mt++)
        #pragma unroll
        for (int j = 0; j < 4; j++)
            #pragma unroll
            for (int r = 0; r < 4; r++) acc[mt][j][r] = 0.f;

    #pragma unroll 1
    for (int g = 0; g <= cnt; g++) {
        const __half* Asrc;
        int mat;
        if (g < cnt) {
            int i = c_dstedges[t][g];
            Asrc = d_agg[i];
            mat = layer * 24 + i;
        } else {
            Asrc = d_xh[pin][t];
            mat = 72 + layer * 6 + t;
        }

        // ---- A tile: fp16 direct copy into padded smem ----
        const uint4* As = (const uint4*)Asrc;
        #pragma unroll
        for (int q = 0; q < 8; q++) {
            int idx = tid + q * 256;          // 2048 = 128 rows x 16 uint4
            int row = idx >> 4, c = idx & 15;
            uint4 v = make_uint4(0u, 0u, 0u, 0u);
            int gr = r0 + row;
            if (gr < NN) v = __ldg(As + (size_t)gr * 16 + c);
            *(uint4*)(smem + (size_t)(row * ASTRIDE + c * 8) * 2) = v;
        }
        __syncthreads();

        const uint4* Bf = d_bfrag[mat];
        #pragma unroll
        for (int ks = 0; ks < 8; ks++) {
            uint32_t ah[4][4];
            #pragma unroll
            for (int mt = 0; mt < 4; mt++) {
                uint32_t off = (uint32_t)(((wr * 64 + mt * 16 + (l & 15)) * ASTRIDE
                                           + ks * 16 + (l >> 4) * 8) * 2);
                asm volatile("ldmatrix.sync.aligned.m8n8.x4.shared.b16 {%0,%1,%2,%3}, [%4];"
                    : "=r"(ah[mt][0]), "=r"(ah[mt][1]), "=r"(ah[mt][2]), "=r"(ah[mt][3])
                    : "r"(sb + off));
            }
            #pragma unroll
            for (int j = 0; j < 4; j++) {
                int fidx = (ks * 16 + wc * 4 + j) * 32 + l;
                uint4 b = __ldg(Bf + fidx);   // {hi.x, hi.y, lo.x, lo.y}
                #pragma unroll
                for (int mt = 0; mt < 4; mt++) {
                    float* c = acc[mt][j];
                    asm volatile("mma.sync.aligned.m16n8k16.row.col.f32.f16.f16.f32 "
                        "{%0,%1,%2,%3}, {%4,%5,%6,%7}, {%8,%9}, {%0,%1,%2,%3};"
                        : "+f"(c[0]), "+f"(c[1]), "+f"(c[2]), "+f"(c[3])
                        : "r"(ah[mt][0]), "r"(ah[mt][1]), "r"(ah[mt][2]), "r"(ah[mt][3]),
                          "r"(b.x), "r"(b.y));
                    asm volatile("mma.sync.aligned.m16n8k16.row.col.f32.f16.f16.f32 "
                        "{%0,%1,%2,%3}, {%4,%5,%6,%7}, {%8,%9}, {%0,%1,%2,%3};"
                        : "+f"(c[0]), "+f"(c[1]), "+f"(c[2]), "+f"(c[3])
                        : "r"(ah[mt][0]), "r"(ah[mt][1]), "r"(ah[mt][2]), "r"(ah[mt][3]),
                          "r"(b.z), "r"(b.w));
                }
            }
        }
        __syncthreads();
    }

    // ---- single epilogue: bias + relu + fp16 store ----
    __half* X = d_xh[pout][t];
    const float* bias = d_blsum[layer][t];
    #pragma unroll
    for (int mt = 0; mt < 4; mt++) {
        int gr = r0 + wr * 64 + mt * 16 + (l >> 2);
        #pragma unroll
        for (int j = 0; j < 4; j++) {
            int tcol = wc * 32 + j * 8 + (l & 3) * 2;
            float b0 = bias[tcol], b1 = bias[tcol + 1];
            float* c = acc[mt][j];
            if (gr < NN)
                ((uint32_t*)(X + (size_t)gr * HIDD))[tcol >> 1] =
                    pack_half2(fmaxf(c[0] + b0, 0.f), fmaxf(c[1] + b1, 0.f));
            if (gr + 8 < NN)
                ((uint32_t*)(X + (size_t)(gr + 8) * HIDD))[tcol >> 1] =
                    pack_half2(fmaxf(c[2] + b0, 0.f), fmaxf(c[3] + b1, 0.f));
        }
    }
}

// ---------------- readout: warp per node, vectorized reduction into g ----------------
__global__ void k_gpp(int pfin, const int* __restrict__ batch) {
    int gw = (blockIdx.x * blockDim.x + threadIdx.x) >> 5;   // node slot 0..6*NN-1
    if (gw >= 6 * NN) return;
    int lane = threadIdx.x & 31;
    int t = gw / NN, n = gw - t * NN;
    float4 v;
    if (t < 4) {
        v = *(const float4*)(d_init[t] + (size_t)n * HIDD + lane * 4);
    } else {
        uint2 u = __ldg((const uint2*)d_xh[pfin][t] + (size_t)n * 32 + lane);
        float2 f0 = __half22float2(*(__half2*)&u.x);
        float2 f1 = __half22float2(*(__half2*)&u.y);
        v = make_float4(f0.x, f0.y, f1.x, f1.y);
    }
    int bg = __ldg(batch + (size_t)t * NN + n);
    float* op = d_g + (size_t)bg * HIDD + lane * 4;
    asm volatile("red.global.add.v4.f32 [%0], {%1,%2,%3,%4};"
                 :: "l"(op), "f"(v.x), "f"(v.y), "f"(v.z), "f"(v.w) : "memory");
}

// ---------------- graph MLP head ----------------
__global__ void k_mlp(float* __restrict__ out,
                      const float* __restrict__ W1, const float* __restrict__ b1,
                      const float* __restrict__ W2, const float* __restrict__ b2) {
    __shared__ float s[4][HIDD];
    int warp = threadIdx.x >> 5, lane = threadIdx.x & 31;
    int gidx = blockIdx.x * 4 + warp;
    if (gidx >= GG) return;
    #pragma unroll
    for (int q = 0; q < 4; q++) {
        float v = d_g[(size_t)gidx * HIDD + lane + q * 32];
        s[warp][lane + q * 32] = fmaxf(v, 0.f);
    }
    __syncwarp();
    float h = b1[lane];
    #pragma unroll 8
    for (int k = 0; k < HIDD; k++) h += s[warp][k] * W1[k * 32 + lane];
    h = fmaxf(h, 0.f);
    float val = h * W2[lane];
    #pragma unroll
    for (int off = 16; off; off >>= 1) val += __shfl_xor_sync(0xffffffffu, val, off);
    if (lane == 0) out[gidx] = val + b2[0];
}

// ---------------- launch ----------------
extern "C" void kernel_launch(void* const* d_in, const int* in_sizes, int n_in,
                              void* d_out, int out_size) {
    const float* Wl   = (const float*)d_in[16];
    const float* bl   = (const float*)d_in[17];
    const float* Wr   = (const float*)d_in[18];
    const float* W1   = (const float*)d_in[19];
    const float* b1   = (const float*)d_in[20];
    const float* W2   = (const float*)d_in[21];
    const float* b2   = (const float*)d_in[22];
    const int* times  = (const int*)d_in[23];
    const int* edges  = (const int*)d_in[24];
    const int* batch  = (const int*)d_in[25];

    cudaFuncSetAttribute(k_gemm_mma, cudaFuncAttributeMaxDynamicSharedMemorySize, SMEM_TOTAL);

    k_zero<<<9375, 256>>>();
    k_deg<<<dim3(391, 24), 1024>>>(edges);
    k_scan1<<<dim3(98, 24), 1024>>>();
    k_scan2<<<24, 32>>>();
    k_scan3<<<dim3(98, 24), 1024>>>();
    k_fill<<<dim3(391, 24), 1024>>>(edges);

    k_wrsum<<<18, 256>>>(Wr, bl);
    k_wprep<<<90, 256>>>(Wl);

    EmbedArgs ea;
    for (int t = 0; t < 4; t++) ea.feat[t] = (const float*)d_in[t];
    for (int t = 0; t < 6; t++) {
        ea.W[t] = (const float*)d_in[4 + 2 * t];
        ea.b[t] = (const float*)d_in[5 + 2 * t];
    }
    ea.times = times;
    k_embed<<<dim3(1563, 6), 128>>>(ea);

    int pin = 0;
    for (int layer = 0; layer < 3; ++layer) {
        int pout = pin ^ 1;
        k_gather<<<dim3(12500, 24), 256>>>(pin);
        k_gemm_mma<<<dim3(782, 6), 256, SMEM_TOTAL>>>(layer, pin, pout);
        pin = pout;
    }

    k_gpp<<<75000, 256>>>(pin, batch);
    k_mlp<<<128, 128>>>((float*)d_out, W1, b1, W2, b2);
}